// round 11
// baseline (speedup 1.0000x reference)
#include <cuda_runtime.h>
#include <cuda_fp16.h>
#include <cstdint>

#define Bsz  16
#define Cch  32
#define Himg 256
#define Wimg 256

#define TILE_H 16
#define TILE_W 32
#define HALO_W 34
#define NPIX   612            // 18 rows x 34 cols

#define THREADS 256

// smem byte offsets
#define A_OFF    0
#define WH_OFF   (NPIX * 64)             // 39168
#define BIAS_OFF (WH_OFF + 9 * 2048)     // 57600
#define GATE_OFF (BIAS_OFF + 128)
#define SMEM_BYTES (GATE_OFF + 128)      // 57856  -> 3 CTAs/SM

// h scratch: per pixel 32 fp16 = 16 uint32, single plane. 64 MB.
#define HPIX   (16u * 65536u)            // Bsz*Himg*Wimg
__device__ uint32_t g_h[(size_t)HPIX * 16u];

// ---------------- helpers ----------------
__device__ __forceinline__ uint32_t smem_u32(const void* p) {
    uint32_t a;
    asm("{ .reg .u64 t; cvta.to.shared.u64 t, %1; cvt.u32.u64 %0, t; }"
        : "=r"(a) : "l"(p));
    return a;
}
__device__ __forceinline__ void ldmx4(uint32_t* d, uint32_t a) {
    asm volatile("ldmatrix.sync.aligned.m8n8.x4.shared.b16 {%0,%1,%2,%3}, [%4];"
                 : "=r"(d[0]), "=r"(d[1]), "=r"(d[2]), "=r"(d[3]) : "r"(a));
}
__device__ __forceinline__ void ldmx4t(uint32_t* d, uint32_t a) {
    asm volatile("ldmatrix.sync.aligned.m8n8.x4.trans.shared.b16 {%0,%1,%2,%3}, [%4];"
                 : "=r"(d[0]), "=r"(d[1]), "=r"(d[2]), "=r"(d[3]) : "r"(a));
}
// fp16-accumulate HMMA: C/D are 2 packed half2 regs
__device__ __forceinline__ void mma16816h(uint32_t* c, const uint32_t* a, const uint32_t* b) {
    asm volatile("mma.sync.aligned.m16n8k16.row.col.f16.f16.f16.f16 "
                 "{%0,%1}, {%2,%3,%4,%5}, {%6,%7}, {%0,%1};"
                 : "+r"(c[0]), "+r"(c[1])
                 : "r"(a[0]), "r"(a[1]), "r"(a[2]), "r"(a[3]),
                   "r"(b[0]), "r"(b[1]));
}

// A-tile: pixel p -> 64B (4 granules of 16B = 8 ci fp16).
__device__ __forceinline__ uint32_t a_byte(int p, int kc) {
    return (uint32_t)(p * 64 + (((kc + p + (p >> 2)) & 3) << 4));
}
// W-tile within one tap: row ci (64B = 32 co fp16), granule nb = co/8
__device__ __forceinline__ uint32_t w_byte(int ci, int nb) {
    return (uint32_t)(ci * 64 + (((nb + ((ci >> 1) & 3)) & 3) << 4));
}

// ---------------- kernel ----------------
template <bool SECOND>
__global__ __launch_bounds__(THREADS, 3)
void conv_hmma(const float* __restrict__ x,
               const float* __restrict__ w,
               const float* __restrict__ bias,
               const float* __restrict__ gate,
               float* __restrict__ out)
{
    extern __shared__ char sm[];
    const uint32_t smb = smem_u32(sm);
    const int tid = threadIdx.x;
    const int b  = blockIdx.z;
    const int y0 = blockIdx.y * TILE_H;
    const int x0 = blockIdx.x * TILE_W;

    // ---- weights -> [tap][ci][co] fp16, swizzled ----
    for (int i = tid; i < Cch * Cch * 9; i += THREADS) {
        int co = i / 288, rem = i - co * 288;
        int ci = rem / 9, tap = rem - ci * 9;
        uint32_t byte = tap * 2048 + w_byte(ci, co >> 3) + ((co & 7) << 1);
        *(__half*)(sm + WH_OFF + byte) = __float2half(w[i]);
    }
    if (tid < 32) {
        ((float*)(sm + BIAS_OFF))[tid] = bias[tid];
        float g = gate[b * 32 + tid];
        ((float*)(sm + GATE_OFF))[tid] = (g > 0.0f) ? g : 0.0f;
    }

    // ---- A tile fill (channels-last fp16, swizzled) ----
    if (!SECOND) {
        for (int i = tid; i < NPIX * 32; i += THREADS) {
            int ci = i / NPIX, p = i - ci * NPIX;
            int gy = y0 - 1 + p / HALO_W;
            int gx = x0 - 1 + p % HALO_W;
            float v = 0.0f;
            if ((unsigned)gy < (unsigned)Himg && (unsigned)gx < (unsigned)Wimg)
                v = x[(((size_t)b * Cch + ci) * Himg + gy) * Wimg + gx];
            *(__half*)(sm + A_OFF + a_byte(p, ci >> 3) + ((ci & 7) << 1)) =
                __float2half(v);
        }
    } else {
        const uint4* gh4 = (const uint4*)g_h;
        for (int i = tid; i < NPIX * 4; i += THREADS) {
            int p = i >> 2, chunk = i & 3;
            int gy = y0 - 1 + p / HALO_W;
            int gx = x0 - 1 + p % HALO_W;
            uint4 vh = make_uint4(0, 0, 0, 0);
            if ((unsigned)gy < (unsigned)Himg && (unsigned)gx < (unsigned)Wimg) {
                size_t pix = (size_t)b * 65536 + gy * 256 + gx;
                vh = gh4[pix * 4 + chunk];
            }
            *(uint4*)(sm + A_OFF + a_byte(p, chunk)) = vh;
        }
    }
    __syncthreads();

    // ---- compute: warp = 4 output rows x 16 px; one A frag per input row ----
    const int wid  = tid >> 5;            // 0..7
    const int lane = tid & 31;
    const int r0   = (wid >> 1) * 4;      // output rows r0 .. r0+3
    const int mbw  = wid & 1;             // 16-px half of the 32-px tile
    const int lm   = lane & 15;
    const int ksel = (lane >> 4) & 1;     // A: k-granule select; B: n-block half

    uint32_t acc[4][4][2];                // [row][nb][2 half2]
    #pragma unroll
    for (int rr = 0; rr < 4; rr++)
        #pragma unroll
        for (int nb = 0; nb < 4; nb++) {
            acc[rr][nb][0] = 0u;
            acc[rr][nb][1] = 0u;
        }

    #pragma unroll
    for (int kb = 0; kb < 2; kb++) {
        const int krow = kb * 16 + lm;
        #pragma unroll
        for (int dx = 0; dx < 3; dx++) {
            // B frags for the 3 dy taps of this dx column (live: 24 regs)
            uint32_t Bh[3][2][4];
            #pragma unroll
            for (int dy = 0; dy < 3; dy++)
                #pragma unroll
                for (int np = 0; np < 2; np++)
                    ldmx4t(Bh[dy][np],
                           smb + WH_OFF + (dy * 3 + dx) * 2048
                               + w_byte(krow, np * 2 + ksel));
            // stream input rows, scatter to accumulator rows
            #pragma unroll
            for (int t = 0; t < 6; t++) {
                uint32_t Ah[4];
                const int p = (r0 + t) * HALO_W + dx + mbw * 16 + lm;
                ldmx4(Ah, smb + A_OFF + a_byte(p, kb * 2 + ksel));
                #pragma unroll
                for (int dy = 0; dy < 3; dy++) {
                    const int rr = t - dy;
                    if (rr >= 0 && rr < 4) {
                        #pragma unroll
                        for (int np = 0; np < 2; np++) {
                            mma16816h(acc[rr][np * 2],     Ah, &Bh[dy][np][0]);
                            mma16816h(acc[rr][np * 2 + 1], Ah, &Bh[dy][np][2]);
                        }
                    }
                }
            }
        }
    }

    // ---- epilogue ----
    const float* bs = (const float*)(sm + BIAS_OFF);
    const float* gs = (const float*)(sm + GATE_OFF);
    const int grp = lane >> 2, tig = lane & 3;

    #pragma unroll
    for (int rr = 0; rr < 4; rr++) {
        const int y = y0 + r0 + rr;
        #pragma unroll
        for (int half = 0; half < 2; half++) {
            const int xg = x0 + mbw * 16 + grp + half * 8;
            #pragma unroll
            for (int nb = 0; nb < 4; nb++) {
                const int co = nb * 8 + tig * 2;
                __half2 hv = *reinterpret_cast<__half2*>(&acc[rr][nb][half]);
                float v0 = __low2float(hv);
                float v1 = __high2float(hv);
                float t0 = fmaxf((v0 + bs[co])     * gs[co],     0.0f);
                float t1 = fmaxf((v1 + bs[co + 1]) * gs[co + 1], 0.0f);
                if (SECOND) {
                    size_t i0 = (((size_t)b * Cch + co)     * Himg + y) * Wimg + xg;
                    size_t i1 = (((size_t)b * Cch + co + 1) * Himg + y) * Wimg + xg;
                    out[i0] = t0 + x[i0];
                    out[i1] = t1 + x[i1];
                } else {
                    __half h0 = __float2half(t0);
                    __half h1 = __float2half(t1);
                    uint32_t uh = (uint32_t)__half_as_ushort(h0)
                                | ((uint32_t)__half_as_ushort(h1) << 16);
                    size_t pix = (size_t)b * 65536 + y * 256 + xg;
                    g_h[pix * 16 + (co >> 1)] = uh;
                }
            }
        }
    }
}

extern "C" void kernel_launch(void* const* d_in, const int* in_sizes, int n_in,
                              void* d_out, int out_size)
{
    const float* x    = (const float*)d_in[0];
    const float* gate = (const float*)d_in[1];
    const float* w1   = (const float*)d_in[2];
    const float* b1   = (const float*)d_in[3];
    const float* w2   = (const float*)d_in[4];
    const float* b2   = (const float*)d_in[5];
    float*       out  = (float*)d_out;
    (void)in_sizes; (void)n_in; (void)out_size;

    cudaFuncSetAttribute(conv_hmma<false>,
                         cudaFuncAttributeMaxDynamicSharedMemorySize, SMEM_BYTES);
    cudaFuncSetAttribute(conv_hmma<true>,
                         cudaFuncAttributeMaxDynamicSharedMemorySize, SMEM_BYTES);

    dim3 grid(Wimg / TILE_W, Himg / TILE_H, Bsz);   // 8 x 16 x 16 = 2048 CTAs

    conv_hmma<false><<<grid, THREADS, SMEM_BYTES>>>(x, w1, b1, gate, nullptr);
    conv_hmma<true ><<<grid, THREADS, SMEM_BYTES>>>(x, w2, b2, gate, out);
}

// round 12
// speedup vs baseline: 1.0630x; 1.0630x over previous
#include <cuda_runtime.h>
#include <cuda_fp16.h>
#include <cstdint>

#define Bsz  16
#define Cch  32
#define Himg 256
#define Wimg 256

#define TILE_H 16
#define TILE_W 32
#define HALO_W 34
#define NPIX   612            // 18 rows x 34 cols

#define THREADS 256

// smem byte offsets
#define A_OFF    0
#define WH_OFF   (NPIX * 64)             // 39168
#define BIAS_OFF (WH_OFF + 9 * 2048)     // 57600
#define GATE_OFF (BIAS_OFF + 128)
#define SMEM_BYTES (GATE_OFF + 128)      // 57856  -> 3 CTAs/SM

// h scratch: per pixel 32 fp16 = 16 uint32, single plane. 64 MB.
#define HPIX   (16u * 65536u)            // Bsz*Himg*Wimg
__device__ uint32_t g_h[(size_t)HPIX * 16u];

// ---------------- helpers ----------------
__device__ __forceinline__ uint32_t smem_u32(const void* p) {
    uint32_t a;
    asm("{ .reg .u64 t; cvta.to.shared.u64 t, %1; cvt.u32.u64 %0, t; }"
        : "=r"(a) : "l"(p));
    return a;
}
__device__ __forceinline__ void ldmx4(uint32_t* d, uint32_t a) {
    asm volatile("ldmatrix.sync.aligned.m8n8.x4.shared.b16 {%0,%1,%2,%3}, [%4];"
                 : "=r"(d[0]), "=r"(d[1]), "=r"(d[2]), "=r"(d[3]) : "r"(a));
}
__device__ __forceinline__ void ldmx4t(uint32_t* d, uint32_t a) {
    asm volatile("ldmatrix.sync.aligned.m8n8.x4.trans.shared.b16 {%0,%1,%2,%3}, [%4];"
                 : "=r"(d[0]), "=r"(d[1]), "=r"(d[2]), "=r"(d[3]) : "r"(a));
}
// fp16-accumulate HMMA: C/D are 2 packed half2 regs
__device__ __forceinline__ void mma16816h(uint32_t* c, const uint32_t* a, const uint32_t* b) {
    asm volatile("mma.sync.aligned.m16n8k16.row.col.f16.f16.f16.f16 "
                 "{%0,%1}, {%2,%3,%4,%5}, {%6,%7}, {%0,%1};"
                 : "+r"(c[0]), "+r"(c[1])
                 : "r"(a[0]), "r"(a[1]), "r"(a[2]), "r"(a[3]),
                   "r"(b[0]), "r"(b[1]));
}

// A-tile: pixel p -> 64B (4 granules of 16B = 8 ci fp16).
__device__ __forceinline__ uint32_t a_byte(int p, int kc) {
    return (uint32_t)(p * 64 + (((kc + p + (p >> 2)) & 3) << 4));
}
// W-tile within one tap: row ci (64B = 32 co fp16), granule nb = co/8
__device__ __forceinline__ uint32_t w_byte(int ci, int nb) {
    return (uint32_t)(ci * 64 + (((nb + ((ci >> 1) & 3)) & 3) << 4));
}

// ---------------- kernel ----------------
template <bool SECOND>
__global__ __launch_bounds__(THREADS, 3)
void conv_hmma(const float* __restrict__ x,
               const float* __restrict__ w,
               const float* __restrict__ bias,
               const float* __restrict__ gate,
               float* __restrict__ out)
{
    extern __shared__ char sm[];
    const uint32_t smb = smem_u32(sm);
    const int tid = threadIdx.x;
    const int b  = blockIdx.z;
    const int y0 = blockIdx.y * TILE_H;
    const int x0 = blockIdx.x * TILE_W;

    // ---- weights -> [tap][ci][co] fp16, swizzled ----
    for (int i = tid; i < Cch * Cch * 9; i += THREADS) {
        int co = i / 288, rem = i - co * 288;
        int ci = rem / 9, tap = rem - ci * 9;
        uint32_t byte = tap * 2048 + w_byte(ci, co >> 3) + ((co & 7) << 1);
        *(__half*)(sm + WH_OFF + byte) = __float2half(w[i]);
    }
    if (tid < 32) {
        ((float*)(sm + BIAS_OFF))[tid] = bias[tid];
        float g = gate[b * 32 + tid];
        ((float*)(sm + GATE_OFF))[tid] = (g > 0.0f) ? g : 0.0f;
    }

    // ---- A tile fill (channels-last fp16, swizzled) ----
    if (!SECOND) {
        // interior: 32 ci x 18 rows x 8 float4-quads (cols 1..32, always in-bounds in x)
        for (int i = tid; i < 32 * 18 * 8; i += THREADS) {
            int ci  = i / 144;
            int rem = i - ci * 144;
            int r   = rem >> 3;
            int q   = rem & 7;
            int gy  = y0 - 1 + r;
            int p   = r * HALO_W + 1 + q * 4;
            const int kc  = ci >> 3;
            const int sub = (ci & 7) << 1;
            float4 v4 = make_float4(0.f, 0.f, 0.f, 0.f);
            if ((unsigned)gy < (unsigned)Himg)
                v4 = *(const float4*)&x[(((size_t)b * Cch + ci) * Himg + gy) * Wimg
                                        + x0 + q * 4];
            *(__half*)(sm + A_OFF + a_byte(p,     kc) + sub) = __float2half(v4.x);
            *(__half*)(sm + A_OFF + a_byte(p + 1, kc) + sub) = __float2half(v4.y);
            *(__half*)(sm + A_OFF + a_byte(p + 2, kc) + sub) = __float2half(v4.z);
            *(__half*)(sm + A_OFF + a_byte(p + 3, kc) + sub) = __float2half(v4.w);
        }
        // edges: cols p%34 == 0 and 33
        for (int i = tid; i < 32 * 18 * 2; i += THREADS) {
            int ci  = i / 36;
            int rem = i - ci * 36;
            int r   = rem >> 1;
            int e   = rem & 1;
            int gy  = y0 - 1 + r;
            int gx  = x0 - 1 + e * 33;
            int p   = r * HALO_W + e * 33;
            float v = 0.0f;
            if ((unsigned)gy < (unsigned)Himg && (unsigned)gx < (unsigned)Wimg)
                v = x[(((size_t)b * Cch + ci) * Himg + gy) * Wimg + gx];
            *(__half*)(sm + A_OFF + a_byte(p, ci >> 3) + ((ci & 7) << 1)) =
                __float2half(v);
        }
    } else {
        const uint4* gh4 = (const uint4*)g_h;
        for (int i = tid; i < NPIX * 4; i += THREADS) {
            int p = i >> 2, chunk = i & 3;
            int gy = y0 - 1 + p / HALO_W;
            int gx = x0 - 1 + p % HALO_W;
            uint4 vh = make_uint4(0, 0, 0, 0);
            if ((unsigned)gy < (unsigned)Himg && (unsigned)gx < (unsigned)Wimg) {
                uint32_t pix = ((uint32_t)b << 16) + gy * 256 + gx;
                vh = gh4[pix * 4 + chunk];
            }
            *(uint4*)(sm + A_OFF + a_byte(p, chunk)) = vh;
        }
    }
    __syncthreads();

    // ---- compute: warp = 4 output rows x 16 px; one A frag per input row ----
    const int wid  = tid >> 5;            // 0..7
    const int lane = tid & 31;
    const int r0   = (wid >> 1) * 4;      // output rows r0 .. r0+3
    const int mbw  = wid & 1;             // 16-px half of the 32-px tile
    const int lm   = lane & 15;
    const int ksel = (lane >> 4) & 1;     // A: k-granule select; B: n-block half

    uint32_t acc[4][4][2];                // [row][nb][2 half2]
    #pragma unroll
    for (int rr = 0; rr < 4; rr++)
        #pragma unroll
        for (int nb = 0; nb < 4; nb++) {
            acc[rr][nb][0] = 0u;
            acc[rr][nb][1] = 0u;
        }

    #pragma unroll
    for (int kb = 0; kb < 2; kb++) {
        const int krow = kb * 16 + lm;
        // hoisted swizzled W offsets for the two n-pairs
        const uint32_t wo0 = smb + WH_OFF + w_byte(krow, ksel);
        const uint32_t wo1 = smb + WH_OFF + w_byte(krow, 2 + ksel);
        #pragma unroll
        for (int dx = 0; dx < 3; dx++) {
            // B frags for the 3 dy taps of this dx column
            uint32_t Bh[3][2][4];
            #pragma unroll
            for (int dy = 0; dy < 3; dy++) {
                const uint32_t tb = (dy * 3 + dx) * 2048;
                ldmx4t(Bh[dy][0], wo0 + tb);
                ldmx4t(Bh[dy][1], wo1 + tb);
            }
            // stream input rows, scatter to accumulator rows
            #pragma unroll
            for (int t = 0; t < 6; t++) {
                uint32_t Ah[4];
                const int p = (r0 + t) * HALO_W + dx + mbw * 16 + lm;
                ldmx4(Ah, smb + A_OFF + a_byte(p, kb * 2 + ksel));
                #pragma unroll
                for (int dy = 0; dy < 3; dy++) {
                    const int rr = t - dy;
                    if (rr >= 0 && rr < 4) {
                        #pragma unroll
                        for (int np = 0; np < 2; np++) {
                            mma16816h(acc[rr][np * 2],     Ah, &Bh[dy][np][0]);
                            mma16816h(acc[rr][np * 2 + 1], Ah, &Bh[dy][np][2]);
                        }
                    }
                }
            }
        }
    }

    // ---- epilogue (32-bit indexing) ----
    const float* bs = (const float*)(sm + BIAS_OFF);
    const float* gs = (const float*)(sm + GATE_OFF);
    const int grp = lane >> 2, tig = lane & 3;

    #pragma unroll
    for (int rr = 0; rr < 4; rr++) {
        const int y = y0 + r0 + rr;
        #pragma unroll
        for (int half = 0; half < 2; half++) {
            const int xg = x0 + mbw * 16 + grp + half * 8;
            const uint32_t obase = ((uint32_t)b << 21) + ((uint32_t)y << 8) + xg;
            const uint32_t hbase = ((((uint32_t)b << 16) + ((uint32_t)y << 8) + xg) << 4);
            #pragma unroll
            for (int nb = 0; nb < 4; nb++) {
                const int co = nb * 8 + tig * 2;
                __half2 hv = *reinterpret_cast<__half2*>(&acc[rr][nb][half]);
                float v0 = __low2float(hv);
                float v1 = __high2float(hv);
                float t0 = fmaxf((v0 + bs[co])     * gs[co],     0.0f);
                float t1 = fmaxf((v1 + bs[co + 1]) * gs[co + 1], 0.0f);
                if (SECOND) {
                    uint32_t i0 = obase + (uint32_t)co * 65536u;
                    out[i0]          = t0 + x[i0];
                    out[i0 + 65536u] = t1 + x[i0 + 65536u];
                } else {
                    __half h0 = __float2half(t0);
                    __half h1 = __float2half(t1);
                    uint32_t uh = (uint32_t)__half_as_ushort(h0)
                                | ((uint32_t)__half_as_ushort(h1) << 16);
                    g_h[hbase + (co >> 1)] = uh;
                }
            }
        }
    }
}

extern "C" void kernel_launch(void* const* d_in, const int* in_sizes, int n_in,
                              void* d_out, int out_size)
{
    const float* x    = (const float*)d_in[0];
    const float* gate = (const float*)d_in[1];
    const float* w1   = (const float*)d_in[2];
    const float* b1   = (const float*)d_in[3];
    const float* w2   = (const float*)d_in[4];
    const float* b2   = (const float*)d_in[5];
    float*       out  = (float*)d_out;
    (void)in_sizes; (void)n_in; (void)out_size;

    cudaFuncSetAttribute(conv_hmma<false>,
                         cudaFuncAttributeMaxDynamicSharedMemorySize, SMEM_BYTES);
    cudaFuncSetAttribute(conv_hmma<true>,
                         cudaFuncAttributeMaxDynamicSharedMemorySize, SMEM_BYTES);

    dim3 grid(Wimg / TILE_W, Himg / TILE_H, Bsz);   // 8 x 16 x 16 = 2048 CTAs

    conv_hmma<false><<<grid, THREADS, SMEM_BYTES>>>(x, w1, b1, gate, nullptr);
    conv_hmma<true ><<<grid, THREADS, SMEM_BYTES>>>(x, w2, b2, gate, out);
}

// round 13
// speedup vs baseline: 1.4292x; 1.3444x over previous
#include <cuda_runtime.h>
#include <cuda_fp16.h>
#include <cstdint>

#define Bsz  16
#define Cch  32
#define Himg 256
#define Wimg 256

#define TILE_H 16
#define TILE_W 32
#define HALO_W 34
#define NPIX   612            // 18 rows x 34 cols

#define THREADS 256

// smem byte offsets
#define A_OFF    0
#define WH_OFF   (NPIX * 64)             // 39168
#define BIAS_OFF (WH_OFF + 9 * 2048)     // 57600
#define GATE_OFF (BIAS_OFF + 128)
#define SMEM_BYTES (GATE_OFF + 128)      // 57856  -> 3 CTAs/SM

// h scratch: per pixel 32 fp16 = 16 uint32, single plane. 64 MB.
#define HPIX   (16u * 65536u)            // Bsz*Himg*Wimg
__device__ uint32_t g_h[(size_t)HPIX * 16u];

// pre-converted weight smem images (fp16, swizzled layout), 18432 B each
__device__ uint4 g_w16[2 * 1152];

// ---------------- helpers ----------------
__device__ __forceinline__ uint32_t smem_u32(const void* p) {
    uint32_t a;
    asm("{ .reg .u64 t; cvta.to.shared.u64 t, %1; cvt.u32.u64 %0, t; }"
        : "=r"(a) : "l"(p));
    return a;
}
__device__ __forceinline__ void ldmx4(uint32_t* d, uint32_t a) {
    asm volatile("ldmatrix.sync.aligned.m8n8.x4.shared.b16 {%0,%1,%2,%3}, [%4];"
                 : "=r"(d[0]), "=r"(d[1]), "=r"(d[2]), "=r"(d[3]) : "r"(a));
}
__device__ __forceinline__ void ldmx4t(uint32_t* d, uint32_t a) {
    asm volatile("ldmatrix.sync.aligned.m8n8.x4.trans.shared.b16 {%0,%1,%2,%3}, [%4];"
                 : "=r"(d[0]), "=r"(d[1]), "=r"(d[2]), "=r"(d[3]) : "r"(a));
}
// fp16-accumulate HMMA: C/D are 2 packed half2 regs
__device__ __forceinline__ void mma16816h(uint32_t* c, const uint32_t* a, const uint32_t* b) {
    asm volatile("mma.sync.aligned.m16n8k16.row.col.f16.f16.f16.f16 "
                 "{%0,%1}, {%2,%3,%4,%5}, {%6,%7}, {%0,%1};"
                 : "+r"(c[0]), "+r"(c[1])
                 : "r"(a[0]), "r"(a[1]), "r"(a[2]), "r"(a[3]),
                   "r"(b[0]), "r"(b[1]));
}
// pack two fp32 -> half2 (lo = first arg)
__device__ __forceinline__ uint32_t cvt2(float lo, float hi) {
    uint32_t d;
    asm("cvt.rn.f16x2.f32 %0, %1, %2;" : "=r"(d) : "f"(hi), "f"(lo));
    return d;
}

// A-tile: pixel p -> 64B (4 granules of 16B = 8 ci fp16).
__device__ __forceinline__ uint32_t a_byte(int p, int kc) {
    return (uint32_t)(p * 64 + (((kc + p + (p >> 2)) & 3) << 4));
}
// W-tile within one tap: row ci (64B = 32 co fp16), granule nb = co/8
__device__ __forceinline__ uint32_t w_byte(int ci, int nb) {
    return (uint32_t)(ci * 64 + (((nb + ((ci >> 1) & 3)) & 3) << 4));
}

// ---------------- weight prep kernel (runs once per launch batch) ----------------
__global__ void prep_weights(const float* __restrict__ w1,
                             const float* __restrict__ w2)
{
    int i = blockIdx.x * 256 + threadIdx.x;      // 0 .. 18431
    if (i >= 2 * 9216) return;
    int sel = i >= 9216;
    int j   = i - sel * 9216;
    int co  = j / 288;
    int rem = j - co * 288;
    int ci  = rem / 9;
    int tap = rem - ci * 9;
    uint32_t byte = tap * 2048 + w_byte(ci, co >> 3) + ((co & 7) << 1);
    const float* w = sel ? w2 : w1;
    char* dst = (char*)g_w16 + sel * 18432 + byte;
    *(__half*)dst = __float2half(w[j]);
}

// ---------------- main kernel ----------------
template <bool SECOND>
__global__ __launch_bounds__(THREADS, 3)
void conv_hmma(const float* __restrict__ x,
               const float* __restrict__ w,     // unused (pre-converted)
               const float* __restrict__ bias,
               const float* __restrict__ gate,
               float* __restrict__ out)
{
    extern __shared__ char sm[];
    const uint32_t smb = smem_u32(sm);
    const int tid = threadIdx.x;
    const int b  = blockIdx.z;
    const int y0 = blockIdx.y * TILE_H;
    const int x0 = blockIdx.x * TILE_W;
    (void)w;

    // ---- weights: straight image copy (coalesced, conflict-free) ----
    {
        const uint4* wsrc = g_w16 + (SECOND ? 1152 : 0);
        uint4* wdst = (uint4*)(sm + WH_OFF);
        #pragma unroll
        for (int k = 0; k < 5; k++) {
            int i = tid + k * THREADS;
            if (i < 1152) wdst[i] = wsrc[i];
        }
    }
    if (tid < 32) {
        ((float*)(sm + BIAS_OFF))[tid] = bias[tid];
        float g = gate[b * 32 + tid];
        ((float*)(sm + GATE_OFF))[tid] = (g > 0.0f) ? g : 0.0f;
    }

    // ---- A tile fill (channels-last fp16, swizzled) ----
    if (!SECOND) {
        // interior: 16 ci-pairs x 18 rows x 8 quads (cols 1..32)
        for (int i = tid; i < 16 * 18 * 8; i += THREADS) {
            int cp  = i / 144;
            int rem = i - cp * 144;
            int r   = rem >> 3;
            int q   = rem & 7;
            int gy  = y0 - 1 + r;
            int p0  = r * HALO_W + 1 + q * 4;
            const int kc  = cp >> 2;
            const int sub = (cp & 3) << 2;
            float4 va = make_float4(0.f, 0.f, 0.f, 0.f), vb = va;
            if ((unsigned)gy < (unsigned)Himg) {
                const float* src = &x[(((size_t)b * Cch + cp * 2) * Himg + gy) * Wimg
                                      + x0 + q * 4];
                va = *(const float4*)src;
                vb = *(const float4*)(src + Himg * Wimg);
            }
            *(uint32_t*)(sm + A_OFF + a_byte(p0,     kc) + sub) = cvt2(va.x, vb.x);
            *(uint32_t*)(sm + A_OFF + a_byte(p0 + 1, kc) + sub) = cvt2(va.y, vb.y);
            *(uint32_t*)(sm + A_OFF + a_byte(p0 + 2, kc) + sub) = cvt2(va.z, vb.z);
            *(uint32_t*)(sm + A_OFF + a_byte(p0 + 3, kc) + sub) = cvt2(va.w, vb.w);
        }
        // edges: cols 0 and 33
        for (int i = tid; i < 16 * 18 * 2; i += THREADS) {
            int cp  = i / 36;
            int rem = i - cp * 36;
            int r   = rem >> 1;
            int e   = rem & 1;
            int gy  = y0 - 1 + r;
            int gx  = x0 - 1 + e * 33;
            int p   = r * HALO_W + e * 33;
            float va = 0.f, vb = 0.f;
            if ((unsigned)gy < (unsigned)Himg && (unsigned)gx < (unsigned)Wimg) {
                const float* src = &x[(((size_t)b * Cch + cp * 2) * Himg + gy) * Wimg + gx];
                va = src[0];
                vb = src[Himg * Wimg];
            }
            *(uint32_t*)(sm + A_OFF + a_byte(p, cp >> 2) + ((cp & 3) << 2)) = cvt2(va, vb);
        }
    } else {
        const uint4* gh4 = (const uint4*)g_h;
        for (int i = tid; i < NPIX * 4; i += THREADS) {
            int p = i >> 2, chunk = i & 3;
            int gy = y0 - 1 + p / HALO_W;
            int gx = x0 - 1 + p % HALO_W;
            uint4 vh = make_uint4(0, 0, 0, 0);
            if ((unsigned)gy < (unsigned)Himg && (unsigned)gx < (unsigned)Wimg) {
                uint32_t pix = ((uint32_t)b << 16) + gy * 256 + gx;
                vh = gh4[pix * 4 + chunk];
            }
            *(uint4*)(sm + A_OFF + a_byte(p, chunk)) = vh;
        }
    }
    __syncthreads();

    // ---- compute: warp = 4 output rows x 16 px; one A frag per input row ----
    const int wid  = tid >> 5;            // 0..7
    const int lane = tid & 31;
    const int r0   = (wid >> 1) * 4;      // output rows r0 .. r0+3
    const int mbw  = wid & 1;             // 16-px half of the 32-px tile
    const int lm   = lane & 15;
    const int ksel = (lane >> 4) & 1;     // A: k-granule select; B: n-block half

    uint32_t acc[4][4][2];                // [row][nb][2 half2]
    #pragma unroll
    for (int rr = 0; rr < 4; rr++)
        #pragma unroll
        for (int nb = 0; nb < 4; nb++) {
            acc[rr][nb][0] = 0u;
            acc[rr][nb][1] = 0u;
        }

    #pragma unroll
    for (int kb = 0; kb < 2; kb++) {
        const int krow = kb * 16 + lm;
        const uint32_t wo0 = smb + WH_OFF + w_byte(krow, ksel);
        const uint32_t wo1 = smb + WH_OFF + w_byte(krow, 2 + ksel);
        #pragma unroll
        for (int dx = 0; dx < 3; dx++) {
            uint32_t Bh[3][2][4];
            #pragma unroll
            for (int dy = 0; dy < 3; dy++) {
                const uint32_t tb = (dy * 3 + dx) * 2048;
                ldmx4t(Bh[dy][0], wo0 + tb);
                ldmx4t(Bh[dy][1], wo1 + tb);
            }
            #pragma unroll
            for (int t = 0; t < 6; t++) {
                uint32_t Ah[4];
                const int p = (r0 + t) * HALO_W + dx + mbw * 16 + lm;
                ldmx4(Ah, smb + A_OFF + a_byte(p, kb * 2 + ksel));
                #pragma unroll
                for (int dy = 0; dy < 3; dy++) {
                    const int rr = t - dy;
                    if (rr >= 0 && rr < 4) {
                        #pragma unroll
                        for (int np = 0; np < 2; np++) {
                            mma16816h(acc[rr][np * 2],     Ah, &Bh[dy][np][0]);
                            mma16816h(acc[rr][np * 2 + 1], Ah, &Bh[dy][np][2]);
                        }
                    }
                }
            }
        }
    }

    // ---- epilogue (32-bit indexing) ----
    const float* bs = (const float*)(sm + BIAS_OFF);
    const float* gs = (const float*)(sm + GATE_OFF);
    const int grp = lane >> 2, tig = lane & 3;

    #pragma unroll
    for (int rr = 0; rr < 4; rr++) {
        const int y = y0 + r0 + rr;
        #pragma unroll
        for (int half = 0; half < 2; half++) {
            const int xg = x0 + mbw * 16 + grp + half * 8;
            const uint32_t obase = ((uint32_t)b << 21) + ((uint32_t)y << 8) + xg;
            const uint32_t hbase = ((((uint32_t)b << 16) + ((uint32_t)y << 8) + xg) << 4);
            #pragma unroll
            for (int nb = 0; nb < 4; nb++) {
                const int co = nb * 8 + tig * 2;
                __half2 hv = *reinterpret_cast<__half2*>(&acc[rr][nb][half]);
                float v0 = __low2float(hv);
                float v1 = __high2float(hv);
                float t0 = fmaxf((v0 + bs[co])     * gs[co],     0.0f);
                float t1 = fmaxf((v1 + bs[co + 1]) * gs[co + 1], 0.0f);
                if (SECOND) {
                    uint32_t i0 = obase + (uint32_t)co * 65536u;
                    out[i0]          = t0 + x[i0];
                    out[i0 + 65536u] = t1 + x[i0 + 65536u];
                } else {
                    g_h[hbase + (co >> 1)] = cvt2(t0, t1);
                }
            }
        }
    }
}

extern "C" void kernel_launch(void* const* d_in, const int* in_sizes, int n_in,
                              void* d_out, int out_size)
{
    const float* x    = (const float*)d_in[0];
    const float* gate = (const float*)d_in[1];
    const float* w1   = (const float*)d_in[2];
    const float* b1   = (const float*)d_in[3];
    const float* w2   = (const float*)d_in[4];
    const float* b2   = (const float*)d_in[5];
    float*       out  = (float*)d_out;
    (void)in_sizes; (void)n_in; (void)out_size;

    cudaFuncSetAttribute(conv_hmma<false>,
                         cudaFuncAttributeMaxDynamicSharedMemorySize, SMEM_BYTES);
    cudaFuncSetAttribute(conv_hmma<true>,
                         cudaFuncAttributeMaxDynamicSharedMemorySize, SMEM_BYTES);

    dim3 grid(Wimg / TILE_W, Himg / TILE_H, Bsz);   // 8 x 16 x 16 = 2048 CTAs

    prep_weights<<<72, 256>>>(w1, w2);
    conv_hmma<false><<<grid, THREADS, SMEM_BYTES>>>(x, w1, b1, gate, nullptr);
    conv_hmma<true ><<<grid, THREADS, SMEM_BYTES>>>(x, w2, b2, gate, out);
}

// round 14
// speedup vs baseline: 1.6374x; 1.1457x over previous
#include <cuda_runtime.h>
#include <cuda_fp16.h>
#include <cstdint>

#define Bsz  16
#define Cch  32
#define Himg 256
#define Wimg 256

#define TILE_H 16
#define TILE_W 32
#define HALO_W 34
#define NPIX   612            // 18 rows x 34 cols

#define THREADS 256
#define GRID_P  444           // 148 SMs x 3 CTAs
#define NTILES  2048

// smem byte offsets
#define A_OFF    0
#define WH_OFF   (NPIX * 64)             // 39168
#define BIAS_OFF (WH_OFF + 9 * 2048)     // 57600
#define GATE_OFF (BIAS_OFF + 128)        // 2 slots x 128
#define SMEM_BYTES (GATE_OFF + 256)      // 57984 -> 3 CTAs/SM

// h scratch: per pixel 32 fp16 = 16 uint32, single plane. 64 MB.
#define HPIX   (16u * 65536u)            // Bsz*Himg*Wimg
__device__ uint32_t g_h[(size_t)HPIX * 16u];

// pre-converted weight smem images (fp16, swizzled layout), 18432 B each
__device__ uint4 g_w16[2 * 1152];

// ---------------- helpers ----------------
__device__ __forceinline__ uint32_t smem_u32(const void* p) {
    uint32_t a;
    asm("{ .reg .u64 t; cvta.to.shared.u64 t, %1; cvt.u32.u64 %0, t; }"
        : "=r"(a) : "l"(p));
    return a;
}
__device__ __forceinline__ void ldmx4(uint32_t* d, uint32_t a) {
    asm volatile("ldmatrix.sync.aligned.m8n8.x4.shared.b16 {%0,%1,%2,%3}, [%4];"
                 : "=r"(d[0]), "=r"(d[1]), "=r"(d[2]), "=r"(d[3]) : "r"(a));
}
__device__ __forceinline__ void ldmx4t(uint32_t* d, uint32_t a) {
    asm volatile("ldmatrix.sync.aligned.m8n8.x4.trans.shared.b16 {%0,%1,%2,%3}, [%4];"
                 : "=r"(d[0]), "=r"(d[1]), "=r"(d[2]), "=r"(d[3]) : "r"(a));
}
// fp16-accumulate HMMA: C/D are 2 packed half2 regs
__device__ __forceinline__ void mma16816h(uint32_t* c, const uint32_t* a, const uint32_t* b) {
    asm volatile("mma.sync.aligned.m16n8k16.row.col.f16.f16.f16.f16 "
                 "{%0,%1}, {%2,%3,%4,%5}, {%6,%7}, {%0,%1};"
                 : "+r"(c[0]), "+r"(c[1])
                 : "r"(a[0]), "r"(a[1]), "r"(a[2]), "r"(a[3]),
                   "r"(b[0]), "r"(b[1]));
}
// pack two fp32 -> half2 (lo = first arg)
__device__ __forceinline__ uint32_t cvt2(float lo, float hi) {
    uint32_t d;
    asm("cvt.rn.f16x2.f32 %0, %1, %2;" : "=r"(d) : "f"(hi), "f"(lo));
    return d;
}
// cp.async 16B with zero-fill when bytes==0
__device__ __forceinline__ void cpa16(uint32_t dst, const void* src, uint32_t bytes) {
    asm volatile("cp.async.cg.shared.global [%0], [%1], 16, %2;"
                 :: "r"(dst), "l"(src), "r"(bytes) : "memory");
}
__device__ __forceinline__ void cpa_wait() {
    asm volatile("cp.async.commit_group;\n\tcp.async.wait_group 0;" ::: "memory");
}

// A-tile: pixel p -> 64B (4 granules of 16B = 8 ci fp16).
__device__ __forceinline__ uint32_t a_byte(int p, int kc) {
    return (uint32_t)(p * 64 + (((kc + p + (p >> 2)) & 3) << 4));
}
// W-tile within one tap: row ci (64B = 32 co fp16), granule nb = co/8
__device__ __forceinline__ uint32_t w_byte(int ci, int nb) {
    return (uint32_t)(ci * 64 + (((nb + ((ci >> 1) & 3)) & 3) << 4));
}

// ---------------- weight prep kernel ----------------
__global__ void prep_weights(const float* __restrict__ w1,
                             const float* __restrict__ w2)
{
    int i = blockIdx.x * 256 + threadIdx.x;      // 0 .. 18431
    if (i >= 2 * 9216) return;
    int sel = i >= 9216;
    int j   = i - sel * 9216;
    int co  = j / 288;
    int rem = j - co * 288;
    int ci  = rem / 9;
    int tap = rem - ci * 9;
    uint32_t byte = tap * 2048 + w_byte(ci, co >> 3) + ((co & 7) << 1);
    const float* w = sel ? w2 : w1;
    char* dst = (char*)g_w16 + sel * 18432 + byte;
    *(__half*)dst = __float2half(w[j]);
}

// ---------------- main kernel (persistent) ----------------
template <bool SECOND>
__global__ __launch_bounds__(THREADS, 3)
void conv_hmma(const float* __restrict__ x,
               const float* __restrict__ bias,
               const float* __restrict__ gate,
               float* __restrict__ out)
{
    extern __shared__ char sm[];
    const uint32_t smb = smem_u32(sm);
    const int tid = threadIdx.x;

    // ---- one-time: weights image + bias ----
    {
        const uint4* wsrc = g_w16 + (SECOND ? 1152 : 0);
        uint4* wdst = (uint4*)(sm + WH_OFF);
        #pragma unroll
        for (int k = 0; k < 5; k++) {
            int i = tid + k * THREADS;
            if (i < 1152) wdst[i] = wsrc[i];
        }
        if (tid < 32) ((float*)(sm + BIAS_OFF))[tid] = bias[tid];
    }

    const int wid  = tid >> 5;
    const int lane = tid & 31;
    const int r0   = (wid >> 1) * 4;
    const int mbw  = wid & 1;
    const int lm   = lane & 15;
    const int ksel = (lane >> 4) & 1;
    const int grp  = lane >> 2, tig = lane & 3;

    int it = 0;
    for (int tile = blockIdx.x; tile < NTILES; tile += GRID_P, it++) {
        const int b  = tile >> 7;
        const int y0 = ((tile >> 3) & 15) * TILE_H;
        const int x0 = (tile & 7) * TILE_W;
        const int sl = it & 1;

        // ---- fill A tile + gate slot ----
        if (tid < 32) {
            float g = gate[b * 32 + tid];
            ((float*)(sm + GATE_OFF))[sl * 32 + tid] = (g > 0.0f) ? g : 0.0f;
        }
        if (!SECOND) {
            // interior: 16 ci-pairs x 18 rows x 8 quads (cols 1..32)
            for (int i = tid; i < 16 * 18 * 8; i += THREADS) {
                int cp  = i / 144;
                int rem = i - cp * 144;
                int r   = rem >> 3;
                int q   = rem & 7;
                int gy  = y0 - 1 + r;
                int p0  = r * HALO_W + 1 + q * 4;
                const int kc  = cp >> 2;
                const int sub = (cp & 3) << 2;
                float4 va = make_float4(0.f, 0.f, 0.f, 0.f), vb = va;
                if ((unsigned)gy < (unsigned)Himg) {
                    const float* src = &x[(((size_t)b * Cch + cp * 2) * Himg + gy) * Wimg
                                          + x0 + q * 4];
                    va = *(const float4*)src;
                    vb = *(const float4*)(src + Himg * Wimg);
                }
                *(uint32_t*)(sm + A_OFF + a_byte(p0,     kc) + sub) = cvt2(va.x, vb.x);
                *(uint32_t*)(sm + A_OFF + a_byte(p0 + 1, kc) + sub) = cvt2(va.y, vb.y);
                *(uint32_t*)(sm + A_OFF + a_byte(p0 + 2, kc) + sub) = cvt2(va.z, vb.z);
                *(uint32_t*)(sm + A_OFF + a_byte(p0 + 3, kc) + sub) = cvt2(va.w, vb.w);
            }
            // edges: cols 0 and 33
            for (int i = tid; i < 16 * 18 * 2; i += THREADS) {
                int cp  = i / 36;
                int rem = i - cp * 36;
                int r   = rem >> 1;
                int e   = rem & 1;
                int gy  = y0 - 1 + r;
                int gx  = x0 - 1 + e * 33;
                int p   = r * HALO_W + e * 33;
                float va = 0.f, vb = 0.f;
                if ((unsigned)gy < (unsigned)Himg && (unsigned)gx < (unsigned)Wimg) {
                    const float* src = &x[(((size_t)b * Cch + cp * 2) * Himg + gy) * Wimg + gx];
                    va = src[0];
                    vb = src[Himg * Wimg];
                }
                *(uint32_t*)(sm + A_OFF + a_byte(p, cp >> 2) + ((cp & 3) << 2)) = cvt2(va, vb);
            }
        } else {
            const uint4* gh4 = (const uint4*)g_h;
            for (int i = tid; i < NPIX * 4; i += THREADS) {
                int p = i >> 2, chunk = i & 3;
                int gy = y0 - 1 + p / HALO_W;
                int gx = x0 - 1 + p % HALO_W;
                bool valid = (unsigned)gy < (unsigned)Himg && (unsigned)gx < (unsigned)Wimg;
                uint32_t pix = valid ? (((uint32_t)b << 16) + gy * 256 + gx) : 0u;
                cpa16(smb + A_OFF + a_byte(p, chunk),
                      gh4 + (size_t)pix * 4 + chunk,
                      valid ? 16u : 0u);
            }
            cpa_wait();
        }
        __syncthreads();

        // ---- compute ----
        uint32_t acc[4][4][2];
        #pragma unroll
        for (int rr = 0; rr < 4; rr++)
            #pragma unroll
            for (int nb = 0; nb < 4; nb++) {
                acc[rr][nb][0] = 0u;
                acc[rr][nb][1] = 0u;
            }

        #pragma unroll
        for (int kb = 0; kb < 2; kb++) {
            const int krow = kb * 16 + lm;
            const uint32_t wo0 = smb + WH_OFF + w_byte(krow, ksel);
            const uint32_t wo1 = smb + WH_OFF + w_byte(krow, 2 + ksel);
            #pragma unroll
            for (int dx = 0; dx < 3; dx++) {
                uint32_t Bh[3][2][4];
                #pragma unroll
                for (int dy = 0; dy < 3; dy++) {
                    const uint32_t tb = (dy * 3 + dx) * 2048;
                    ldmx4t(Bh[dy][0], wo0 + tb);
                    ldmx4t(Bh[dy][1], wo1 + tb);
                }
                #pragma unroll
                for (int t = 0; t < 6; t++) {
                    uint32_t Ah[4];
                    const int p = (r0 + t) * HALO_W + dx + mbw * 16 + lm;
                    ldmx4(Ah, smb + A_OFF + a_byte(p, kb * 2 + ksel));
                    #pragma unroll
                    for (int dy = 0; dy < 3; dy++) {
                        const int rr = t - dy;
                        if (rr >= 0 && rr < 4) {
                            #pragma unroll
                            for (int np = 0; np < 2; np++) {
                                mma16816h(acc[rr][np * 2],     Ah, &Bh[dy][np][0]);
                                mma16816h(acc[rr][np * 2 + 1], Ah, &Bh[dy][np][2]);
                            }
                        }
                    }
                }
            }
        }
        __syncthreads();   // A + gate slot free for next iteration's fill

        // ---- epilogue ----
        const float* bs = (const float*)(sm + BIAS_OFF);
        const float* gs = (const float*)(sm + GATE_OFF) + sl * 32;

        #pragma unroll
        for (int rr = 0; rr < 4; rr++) {
            const int y = y0 + r0 + rr;
            #pragma unroll
            for (int half = 0; half < 2; half++) {
                const int xg = x0 + mbw * 16 + grp + half * 8;
                const uint32_t obase = ((uint32_t)b << 21) + ((uint32_t)y << 8) + xg;
                const uint32_t hbase = ((((uint32_t)b << 16) + ((uint32_t)y << 8) + xg) << 4);
                #pragma unroll
                for (int nb = 0; nb < 4; nb++) {
                    const int co = nb * 8 + tig * 2;
                    __half2 hv = *reinterpret_cast<__half2*>(&acc[rr][nb][half]);
                    float v0 = __low2float(hv);
                    float v1 = __high2float(hv);
                    float t0 = fmaxf((v0 + bs[co])     * gs[co],     0.0f);
                    float t1 = fmaxf((v1 + bs[co + 1]) * gs[co + 1], 0.0f);
                    if (SECOND) {
                        uint32_t i0 = obase + (uint32_t)co * 65536u;
                        out[i0]          = t0 + x[i0];
                        out[i0 + 65536u] = t1 + x[i0 + 65536u];
                    } else {
                        g_h[hbase + (co >> 1)] = cvt2(t0, t1);
                    }
                }
            }
        }
    }
}

extern "C" void kernel_launch(void* const* d_in, const int* in_sizes, int n_in,
                              void* d_out, int out_size)
{
    const float* x    = (const float*)d_in[0];
    const float* gate = (const float*)d_in[1];
    const float* w1   = (const float*)d_in[2];
    const float* b1   = (const float*)d_in[3];
    const float* w2   = (const float*)d_in[4];
    const float* b2   = (const float*)d_in[5];
    float*       out  = (float*)d_out;
    (void)in_sizes; (void)n_in; (void)out_size;

    cudaFuncSetAttribute(conv_hmma<false>,
                         cudaFuncAttributeMaxDynamicSharedMemorySize, SMEM_BYTES);
    cudaFuncSetAttribute(conv_hmma<true>,
                         cudaFuncAttributeMaxDynamicSharedMemorySize, SMEM_BYTES);

    prep_weights<<<72, 256>>>(w1, w2);
    conv_hmma<false><<<GRID_P, THREADS, SMEM_BYTES>>>(x, b1, gate, nullptr);
    conv_hmma<true ><<<GRID_P, THREADS, SMEM_BYTES>>>(x, b2, gate, out);
}

// round 15
// speedup vs baseline: 1.7075x; 1.0428x over previous
#include <cuda_runtime.h>
#include <cuda_fp16.h>
#include <cstdint>

#define Bsz  16
#define Cch  32
#define Himg 256
#define Wimg 256

#define TILE_H 16
#define TILE_W 32
#define HALO_W 34
#define NPIX   612            // 18 rows x 34 cols

#define THREADS 256
#define GRID_P  444           // 148 SMs x 3 CTAs
#define NTILES  2048

// smem byte offsets
#define A_OFF    0
#define WH_OFF   (NPIX * 64)             // 39168
#define BIAS_OFF (WH_OFF + 9 * 2048)     // 57600 (16 half2 = 64B)
#define GATE_OFF (BIAS_OFF + 128)        // 2 slots x 16 half2
#define SMEM_BYTES (GATE_OFF + 256)      // 57984 -> 3 CTAs/SM

// h scratch: per pixel 32 fp16 = 16 uint32, single plane. 64 MB.
#define HPIX   (16u * 65536u)            // Bsz*Himg*Wimg
__device__ uint32_t g_h[(size_t)HPIX * 16u];

// pre-converted weight smem images (fp16, swizzled layout), 18432 B each
__device__ uint4 g_w16[2 * 1152];

// ---------------- helpers ----------------
__device__ __forceinline__ uint32_t smem_u32(const void* p) {
    uint32_t a;
    asm("{ .reg .u64 t; cvta.to.shared.u64 t, %1; cvt.u32.u64 %0, t; }"
        : "=r"(a) : "l"(p));
    return a;
}
__device__ __forceinline__ void ldmx4(uint32_t* d, uint32_t a) {
    asm volatile("ldmatrix.sync.aligned.m8n8.x4.shared.b16 {%0,%1,%2,%3}, [%4];"
                 : "=r"(d[0]), "=r"(d[1]), "=r"(d[2]), "=r"(d[3]) : "r"(a));
}
__device__ __forceinline__ void ldmx4t(uint32_t* d, uint32_t a) {
    asm volatile("ldmatrix.sync.aligned.m8n8.x4.trans.shared.b16 {%0,%1,%2,%3}, [%4];"
                 : "=r"(d[0]), "=r"(d[1]), "=r"(d[2]), "=r"(d[3]) : "r"(a));
}
// fp16-accumulate HMMA: C/D are 2 packed half2 regs
__device__ __forceinline__ void mma16816h(uint32_t* c, const uint32_t* a, const uint32_t* b) {
    asm volatile("mma.sync.aligned.m16n8k16.row.col.f16.f16.f16.f16 "
                 "{%0,%1}, {%2,%3,%4,%5}, {%6,%7}, {%0,%1};"
                 : "+r"(c[0]), "+r"(c[1])
                 : "r"(a[0]), "r"(a[1]), "r"(a[2]), "r"(a[3]),
                   "r"(b[0]), "r"(b[1]));
}
// pack two fp32 -> half2 (lo = first arg)
__device__ __forceinline__ uint32_t cvt2(float lo, float hi) {
    uint32_t d;
    asm("cvt.rn.f16x2.f32 %0, %1, %2;" : "=r"(d) : "f"(hi), "f"(lo));
    return d;
}
// cp.async 16B with zero-fill when bytes==0
__device__ __forceinline__ void cpa16(uint32_t dst, const void* src, uint32_t bytes) {
    asm volatile("cp.async.cg.shared.global [%0], [%1], 16, %2;"
                 :: "r"(dst), "l"(src), "r"(bytes) : "memory");
}
__device__ __forceinline__ void cpa_wait() {
    asm volatile("cp.async.commit_group;\n\tcp.async.wait_group 0;" ::: "memory");
}

// A-tile: pixel p -> 64B (4 granules of 16B = 8 ci fp16).
__device__ __forceinline__ uint32_t a_byte(int p, int kc) {
    return (uint32_t)(p * 64 + (((kc + p + (p >> 2)) & 3) << 4));
}
// W-tile within one tap: row ci (64B = 32 co fp16), granule nb = co/8
__device__ __forceinline__ uint32_t w_byte(int ci, int nb) {
    return (uint32_t)(ci * 64 + (((nb + ((ci >> 1) & 3)) & 3) << 4));
}

// ---------------- weight prep kernel ----------------
__global__ void prep_weights(const float* __restrict__ w1,
                             const float* __restrict__ w2)
{
    int i = blockIdx.x * 256 + threadIdx.x;      // 0 .. 18431
    if (i >= 2 * 9216) return;
    int sel = i >= 9216;
    int j   = i - sel * 9216;
    int co  = j / 288;
    int rem = j - co * 288;
    int ci  = rem / 9;
    int tap = rem - ci * 9;
    uint32_t byte = tap * 2048 + w_byte(ci, co >> 3) + ((co & 7) << 1);
    const float* w = sel ? w2 : w1;
    char* dst = (char*)g_w16 + sel * 18432 + byte;
    *(__half*)dst = __float2half(w[j]);
}

// ---------------- main kernel (persistent) ----------------
template <bool SECOND>
__global__ __launch_bounds__(THREADS, 3)
void conv_hmma(const float* __restrict__ x,
               const float* __restrict__ bias,
               const float* __restrict__ gate,
               float* __restrict__ out)
{
    extern __shared__ char sm[];
    const uint32_t smb = smem_u32(sm);
    const int tid = threadIdx.x;

    // ---- one-time: weights image + bias (as half2 pairs) ----
    {
        const uint4* wsrc = g_w16 + (SECOND ? 1152 : 0);
        uint4* wdst = (uint4*)(sm + WH_OFF);
        #pragma unroll
        for (int k = 0; k < 5; k++) {
            int i = tid + k * THREADS;
            if (i < 1152) wdst[i] = wsrc[i];
        }
        if (tid < 16)
            ((__half2*)(sm + BIAS_OFF))[tid] =
                __floats2half2_rn(bias[2 * tid], bias[2 * tid + 1]);
    }

    const int wid  = tid >> 5;
    const int lane = tid & 31;
    const int r0   = (wid >> 1) * 4;
    const int mbw  = wid & 1;
    const int lm   = lane & 15;
    const int ksel = (lane >> 4) & 1;
    const int grp  = lane >> 2, tig = lane & 3;
    const __half2 hz = __float2half2_rn(0.0f);

    int it = 0;
    for (int tile = blockIdx.x; tile < NTILES; tile += GRID_P, it++) {
        const int b  = tile >> 7;
        const int y0 = ((tile >> 3) & 15) * TILE_H;
        const int x0 = (tile & 7) * TILE_W;
        const int sl = it & 1;

        // ---- fill A tile + gate slot (half2, pre-clamped) ----
        if (tid < 16) {
            float g0 = fmaxf(gate[b * 32 + 2 * tid],     0.0f);
            float g1 = fmaxf(gate[b * 32 + 2 * tid + 1], 0.0f);
            ((__half2*)(sm + GATE_OFF))[sl * 16 + tid] = __floats2half2_rn(g0, g1);
        }
        if (!SECOND) {
            // interior: division-free; cp = tid>>4, 9 k-steps cover rem 0..143
            {
                const int cp = tid >> 4;
                const int j  = tid & 15;
                const int kc  = cp >> 2;
                const int sub = (cp & 3) << 2;
                const float* xc = &x[((size_t)b * Cch + cp * 2) * (Himg * Wimg)];
                #pragma unroll
                for (int k = 0; k < 9; k++) {
                    const int rem = j + (k << 4);       // 0..143
                    const int r   = rem >> 3;
                    const int q   = rem & 7;
                    const int gy  = y0 - 1 + r;
                    const int p0  = r * HALO_W + 1 + q * 4;
                    float4 va = make_float4(0.f, 0.f, 0.f, 0.f), vb = va;
                    if ((unsigned)gy < (unsigned)Himg) {
                        const float* src = xc + gy * Wimg + x0 + q * 4;
                        va = *(const float4*)src;
                        vb = *(const float4*)(src + Himg * Wimg);
                    }
                    *(uint32_t*)(sm + A_OFF + a_byte(p0,     kc) + sub) = cvt2(va.x, vb.x);
                    *(uint32_t*)(sm + A_OFF + a_byte(p0 + 1, kc) + sub) = cvt2(va.y, vb.y);
                    *(uint32_t*)(sm + A_OFF + a_byte(p0 + 2, kc) + sub) = cvt2(va.z, vb.z);
                    *(uint32_t*)(sm + A_OFF + a_byte(p0 + 3, kc) + sub) = cvt2(va.w, vb.w);
                }
            }
            // edges: cols 0 and 33
            for (int i = tid; i < 16 * 18 * 2; i += THREADS) {
                int cp  = i / 36;
                int rem = i - cp * 36;
                int r   = rem >> 1;
                int e   = rem & 1;
                int gy  = y0 - 1 + r;
                int gx  = x0 - 1 + e * 33;
                int p   = r * HALO_W + e * 33;
                float va = 0.f, vb = 0.f;
                if ((unsigned)gy < (unsigned)Himg && (unsigned)gx < (unsigned)Wimg) {
                    const float* src = &x[(((size_t)b * Cch + cp * 2) * Himg + gy) * Wimg + gx];
                    va = src[0];
                    vb = src[Himg * Wimg];
                }
                *(uint32_t*)(sm + A_OFF + a_byte(p, cp >> 2) + ((cp & 3) << 2)) = cvt2(va, vb);
            }
        } else {
            const uint4* gh4 = (const uint4*)g_h;
            for (int i = tid; i < NPIX * 4; i += THREADS) {
                int p = i >> 2, chunk = i & 3;
                int gy = y0 - 1 + p / HALO_W;
                int gx = x0 - 1 + p % HALO_W;
                bool valid = (unsigned)gy < (unsigned)Himg && (unsigned)gx < (unsigned)Wimg;
                uint32_t pix = valid ? (((uint32_t)b << 16) + gy * 256 + gx) : 0u;
                cpa16(smb + A_OFF + a_byte(p, chunk),
                      gh4 + (size_t)pix * 4 + chunk,
                      valid ? 16u : 0u);
            }
            cpa_wait();
        }
        __syncthreads();

        // ---- compute ----
        uint32_t acc[4][4][2];
        #pragma unroll
        for (int rr = 0; rr < 4; rr++)
            #pragma unroll
            for (int nb = 0; nb < 4; nb++) {
                acc[rr][nb][0] = 0u;
                acc[rr][nb][1] = 0u;
            }

        #pragma unroll
        for (int kb = 0; kb < 2; kb++) {
            const int krow = kb * 16 + lm;
            const uint32_t wo0 = smb + WH_OFF + w_byte(krow, ksel);
            const uint32_t wo1 = smb + WH_OFF + w_byte(krow, 2 + ksel);
            #pragma unroll
            for (int dx = 0; dx < 3; dx++) {
                uint32_t Bh[3][2][4];
                #pragma unroll
                for (int dy = 0; dy < 3; dy++) {
                    const uint32_t tb = (dy * 3 + dx) * 2048;
                    ldmx4t(Bh[dy][0], wo0 + tb);
                    ldmx4t(Bh[dy][1], wo1 + tb);
                }
                #pragma unroll
                for (int t = 0; t < 6; t++) {
                    uint32_t Ah[4];
                    const int p = (r0 + t) * HALO_W + dx + mbw * 16 + lm;
                    ldmx4(Ah, smb + A_OFF + a_byte(p, kb * 2 + ksel));
                    #pragma unroll
                    for (int dy = 0; dy < 3; dy++) {
                        const int rr = t - dy;
                        if (rr >= 0 && rr < 4) {
                            #pragma unroll
                            for (int np = 0; np < 2; np++) {
                                mma16816h(acc[rr][np * 2],     Ah, &Bh[dy][np][0]);
                                mma16816h(acc[rr][np * 2 + 1], Ah, &Bh[dy][np][2]);
                            }
                        }
                    }
                }
            }
        }
        __syncthreads();   // A + gate slot free for next iteration's fill

        // ---- epilogue (half2 math) ----
        const __half2* bs2 = (const __half2*)(sm + BIAS_OFF);
        const __half2* gs2 = (const __half2*)(sm + GATE_OFF) + sl * 16;
        __half2 b2[4], g2[4];
        #pragma unroll
        for (int nb = 0; nb < 4; nb++) {
            b2[nb] = bs2[nb * 4 + tig];
            g2[nb] = gs2[nb * 4 + tig];
        }

        #pragma unroll
        for (int rr = 0; rr < 4; rr++) {
            const int y = y0 + r0 + rr;
            #pragma unroll
            for (int half = 0; half < 2; half++) {
                const int xg = x0 + mbw * 16 + grp + half * 8;
                const uint32_t obase = ((uint32_t)b << 21) + ((uint32_t)y << 8) + xg;
                const uint32_t hbase = ((((uint32_t)b << 16) + ((uint32_t)y << 8) + xg) << 4);
                #pragma unroll
                for (int nb = 0; nb < 4; nb++) {
                    __half2 a2 = *reinterpret_cast<__half2*>(&acc[rr][nb][half]);
                    __half2 t2 = __hmul2(g2[nb], __hmax2(__hadd2(a2, b2[nb]), hz));
                    if (SECOND) {
                        const int co = nb * 8 + tig * 2;
                        float2 f = __half22float2(t2);
                        uint32_t i0 = obase + (uint32_t)co * 65536u;
                        out[i0]          = f.x + x[i0];
                        out[i0 + 65536u] = f.y + x[i0 + 65536u];
                    } else {
                        const int co = nb * 8 + tig * 2;
                        g_h[hbase + (co >> 1)] = *reinterpret_cast<uint32_t*>(&t2);
                    }
                }
            }
        }
    }
}

extern "C" void kernel_launch(void* const* d_in, const int* in_sizes, int n_in,
                              void* d_out, int out_size)
{
    const float* x    = (const float*)d_in[0];
    const float* gate = (const float*)d_in[1];
    const float* w1   = (const float*)d_in[2];
    const float* b1   = (const float*)d_in[3];
    const float* w2   = (const float*)d_in[4];
    const float* b2   = (const float*)d_in[5];
    float*       out  = (float*)d_out;
    (void)in_sizes; (void)n_in; (void)out_size;

    cudaFuncSetAttribute(conv_hmma<false>,
                         cudaFuncAttributeMaxDynamicSharedMemorySize, SMEM_BYTES);
    cudaFuncSetAttribute(conv_hmma<true>,
                         cudaFuncAttributeMaxDynamicSharedMemorySize, SMEM_BYTES);

    prep_weights<<<72, 256>>>(w1, w2);
    conv_hmma<false><<<GRID_P, THREADS, SMEM_BYTES>>>(x, b1, gate, nullptr);
    conv_hmma<true ><<<GRID_P, THREADS, SMEM_BYTES>>>(x, b2, gate, out);
}

// round 16
// speedup vs baseline: 1.7498x; 1.0248x over previous
#include <cuda_runtime.h>
#include <cuda_fp16.h>
#include <cstdint>

#define Bsz  16
#define Cch  32
#define Himg 256
#define Wimg 256

#define TILE_H 16
#define TILE_W 32
#define HALO_W 34
#define NPIX   612            // 18 rows x 34 cols

#define THREADS 256
#define GRID_P  444           // 148 SMs x 3 CTAs
#define NTILES  2048

// smem byte offsets
#define A_OFF    0
#define WH_OFF   (NPIX * 64)             // 39168
#define BIAS_OFF (WH_OFF + 9 * 2048)     // 57600 (16 half2 = 64B)
#define GATE_OFF (BIAS_OFF + 128)        // 2 slots x 16 half2
#define SMEM_BYTES (GATE_OFF + 256)      // 57984 -> 3 CTAs/SM

// h scratch: per pixel 32 fp16 = 16 uint32, single plane. 64 MB.
#define HPIX   (16u * 65536u)            // Bsz*Himg*Wimg
__device__ uint32_t g_h[(size_t)HPIX * 16u];

// pre-converted weight smem images (fp16, swizzled layout), 18432 B each
__device__ uint4 g_w16[2 * 1152];

// ---------------- helpers ----------------
__device__ __forceinline__ uint32_t smem_u32(const void* p) {
    uint32_t a;
    asm("{ .reg .u64 t; cvta.to.shared.u64 t, %1; cvt.u32.u64 %0, t; }"
        : "=r"(a) : "l"(p));
    return a;
}
__device__ __forceinline__ void ldmx4(uint32_t* d, uint32_t a) {
    asm volatile("ldmatrix.sync.aligned.m8n8.x4.shared.b16 {%0,%1,%2,%3}, [%4];"
                 : "=r"(d[0]), "=r"(d[1]), "=r"(d[2]), "=r"(d[3]) : "r"(a));
}
__device__ __forceinline__ void ldmx4t(uint32_t* d, uint32_t a) {
    asm volatile("ldmatrix.sync.aligned.m8n8.x4.trans.shared.b16 {%0,%1,%2,%3}, [%4];"
                 : "=r"(d[0]), "=r"(d[1]), "=r"(d[2]), "=r"(d[3]) : "r"(a));
}
// fp16-accumulate HMMA: C/D are 2 packed half2 regs
__device__ __forceinline__ void mma16816h(uint32_t* c, const uint32_t* a, const uint32_t* b) {
    asm volatile("mma.sync.aligned.m16n8k16.row.col.f16.f16.f16.f16 "
                 "{%0,%1}, {%2,%3,%4,%5}, {%6,%7}, {%0,%1};"
                 : "+r"(c[0]), "+r"(c[1])
                 : "r"(a[0]), "r"(a[1]), "r"(a[2]), "r"(a[3]),
                   "r"(b[0]), "r"(b[1]));
}
// pack two fp32 -> half2 (lo = first arg)
__device__ __forceinline__ uint32_t cvt2(float lo, float hi) {
    uint32_t d;
    asm("cvt.rn.f16x2.f32 %0, %1, %2;" : "=r"(d) : "f"(hi), "f"(lo));
    return d;
}
// cp.async 16B with zero-fill when bytes==0
__device__ __forceinline__ void cpa16(uint32_t dst, const void* src, uint32_t bytes) {
    asm volatile("cp.async.cg.shared.global [%0], [%1], 16, %2;"
                 :: "r"(dst), "l"(src), "r"(bytes) : "memory");
}
__device__ __forceinline__ void cpa_commit() {
    asm volatile("cp.async.commit_group;" ::: "memory");
}
__device__ __forceinline__ void cpa_waitall() {
    asm volatile("cp.async.wait_group 0;" ::: "memory");
}

// A-tile: pixel p -> 64B (4 granules of 16B = 8 ci fp16).
__device__ __forceinline__ uint32_t a_byte(int p, int kc) {
    return (uint32_t)(p * 64 + (((kc + p + (p >> 2)) & 3) << 4));
}
// W-tile within one tap: row ci (64B = 32 co fp16), granule nb = co/8
__device__ __forceinline__ uint32_t w_byte(int ci, int nb) {
    return (uint32_t)(ci * 64 + (((nb + ((ci >> 1) & 3)) & 3) << 4));
}

// ---------------- weight prep kernel ----------------
__global__ void prep_weights(const float* __restrict__ w1,
                             const float* __restrict__ w2)
{
    int i = blockIdx.x * 256 + threadIdx.x;      // 0 .. 18431
    if (i >= 2 * 9216) return;
    int sel = i >= 9216;
    int j   = i - sel * 9216;
    int co  = j / 288;
    int rem = j - co * 288;
    int ci  = rem / 9;
    int tap = rem - ci * 9;
    uint32_t byte = tap * 2048 + w_byte(ci, co >> 3) + ((co & 7) << 1);
    const float* w = sel ? w2 : w1;
    char* dst = (char*)g_w16 + sel * 18432 + byte;
    *(__half*)dst = __float2half(w[j]);
}

// ---------------- tile fill helpers ----------------
__device__ __forceinline__ void fill_p1(char* sm, const float* __restrict__ x,
                                        int b, int y0, int x0, int tid)
{
    // interior: division-free; cp = tid>>4, 9 k-steps cover rem 0..143
    {
        const int cp = tid >> 4;
        const int j  = tid & 15;
        const int kc  = cp >> 2;
        const int sub = (cp & 3) << 2;
        const float* xc = &x[((size_t)b * Cch + cp * 2) * (Himg * Wimg)];
        #pragma unroll
        for (int k = 0; k < 9; k++) {
            const int rem = j + (k << 4);       // 0..143
            const int r   = rem >> 3;
            const int q   = rem & 7;
            const int gy  = y0 - 1 + r;
            const int p0  = r * HALO_W + 1 + q * 4;
            float4 va = make_float4(0.f, 0.f, 0.f, 0.f), vb = va;
            if ((unsigned)gy < (unsigned)Himg) {
                const float* src = xc + gy * Wimg + x0 + q * 4;
                va = *(const float4*)src;
                vb = *(const float4*)(src + Himg * Wimg);
            }
            *(uint32_t*)(sm + A_OFF + a_byte(p0,     kc) + sub) = cvt2(va.x, vb.x);
            *(uint32_t*)(sm + A_OFF + a_byte(p0 + 1, kc) + sub) = cvt2(va.y, vb.y);
            *(uint32_t*)(sm + A_OFF + a_byte(p0 + 2, kc) + sub) = cvt2(va.z, vb.z);
            *(uint32_t*)(sm + A_OFF + a_byte(p0 + 3, kc) + sub) = cvt2(va.w, vb.w);
        }
    }
    // edges: cols 0 and 33
    for (int i = tid; i < 16 * 18 * 2; i += THREADS) {
        int cp  = i / 36;
        int rem = i - cp * 36;
        int r   = rem >> 1;
        int e   = rem & 1;
        int gy  = y0 - 1 + r;
        int gx  = x0 - 1 + e * 33;
        int p   = r * HALO_W + e * 33;
        float va = 0.f, vb = 0.f;
        if ((unsigned)gy < (unsigned)Himg && (unsigned)gx < (unsigned)Wimg) {
            const float* src = &x[(((size_t)b * Cch + cp * 2) * Himg + gy) * Wimg + gx];
            va = src[0];
            vb = src[Himg * Wimg];
        }
        *(uint32_t*)(sm + A_OFF + a_byte(p, cp >> 2) + ((cp & 3) << 2)) = cvt2(va, vb);
    }
}

__device__ __forceinline__ void prefetch_p1(const float* __restrict__ x,
                                            int b, int y0, int x0, int tid)
{
    const int cp = tid >> 4;
    const int j  = tid & 15;
    const float* xc = &x[((size_t)b * Cch + cp * 2) * (Himg * Wimg)];
    #pragma unroll
    for (int k = 0; k < 9; k++) {
        const int rem = j + (k << 4);
        const int r   = rem >> 3;
        const int q   = rem & 7;
        const int gy  = y0 - 1 + r;
        if ((unsigned)gy < (unsigned)Himg) {
            const float* src = xc + gy * Wimg + x0 + q * 4;
            asm volatile("prefetch.global.L2 [%0];" :: "l"(src));
            asm volatile("prefetch.global.L2 [%0];" :: "l"(src + Himg * Wimg));
        }
    }
}

// issue cp.async fills for pass2 (no wait)
__device__ __forceinline__ void issue_p2(uint32_t smb, int b, int y0, int x0, int tid)
{
    const uint4* gh4 = (const uint4*)g_h;
    for (int i = tid; i < NPIX * 4; i += THREADS) {
        int p = i >> 2, chunk = i & 3;
        int gy = y0 - 1 + p / HALO_W;
        int gx = x0 - 1 + p % HALO_W;
        bool valid = (unsigned)gy < (unsigned)Himg && (unsigned)gx < (unsigned)Wimg;
        uint32_t pix = valid ? (((uint32_t)b << 16) + gy * 256 + gx) : 0u;
        cpa16(smb + A_OFF + a_byte(p, chunk),
              gh4 + (size_t)pix * 4 + chunk,
              valid ? 16u : 0u);
    }
    cpa_commit();
}

// ---------------- main kernel (persistent, pipelined) ----------------
template <bool SECOND>
__global__ __launch_bounds__(THREADS, 3)
void conv_hmma(const float* __restrict__ x,
               const float* __restrict__ bias,
               const float* __restrict__ gate,
               float* __restrict__ out)
{
    extern __shared__ char sm[];
    const uint32_t smb = smem_u32(sm);
    const int tid = threadIdx.x;

    // ---- one-time: weights image + bias (as half2 pairs) ----
    {
        const uint4* wsrc = g_w16 + (SECOND ? 1152 : 0);
        uint4* wdst = (uint4*)(sm + WH_OFF);
        #pragma unroll
        for (int k = 0; k < 5; k++) {
            int i = tid + k * THREADS;
            if (i < 1152) wdst[i] = wsrc[i];
        }
        if (tid < 16)
            ((__half2*)(sm + BIAS_OFF))[tid] =
                __floats2half2_rn(bias[2 * tid], bias[2 * tid + 1]);
    }

    const int wid  = tid >> 5;
    const int lane = tid & 31;
    const int r0   = (wid >> 1) * 4;
    const int mbw  = wid & 1;
    const int lm   = lane & 15;
    const int ksel = (lane >> 4) & 1;
    const int grp  = lane >> 2, tig = lane & 3;
    const __half2 hz = __float2half2_rn(0.0f);

    // ---- prologue: fill first tile ----
    int tile = blockIdx.x;
    {
        const int b  = tile >> 7;
        const int y0 = ((tile >> 3) & 15) * TILE_H;
        const int x0 = (tile & 7) * TILE_W;
        if (tid < 16) {
            float g0 = fmaxf(gate[b * 32 + 2 * tid],     0.0f);
            float g1 = fmaxf(gate[b * 32 + 2 * tid + 1], 0.0f);
            ((__half2*)(sm + GATE_OFF))[tid] = __floats2half2_rn(g0, g1);
        }
        if (!SECOND) fill_p1(sm, x, b, y0, x0, tid);
        else { issue_p2(smb, b, y0, x0, tid); cpa_waitall(); }
    }
    __syncthreads();

    int it = 0;
    while (tile < NTILES) {
        const int b  = tile >> 7;
        const int y0 = ((tile >> 3) & 15) * TILE_H;
        const int x0 = (tile & 7) * TILE_W;
        const int sl = it & 1;

        // ---- compute ----
        uint32_t acc[4][4][2];
        #pragma unroll
        for (int rr = 0; rr < 4; rr++)
            #pragma unroll
            for (int nb = 0; nb < 4; nb++) {
                acc[rr][nb][0] = 0u;
                acc[rr][nb][1] = 0u;
            }

        #pragma unroll
        for (int kb = 0; kb < 2; kb++) {
            const int krow = kb * 16 + lm;
            const uint32_t wo0 = smb + WH_OFF + w_byte(krow, ksel);
            const uint32_t wo1 = smb + WH_OFF + w_byte(krow, 2 + ksel);
            #pragma unroll
            for (int dx = 0; dx < 3; dx++) {
                uint32_t Bh[3][2][4];
                #pragma unroll
                for (int dy = 0; dy < 3; dy++) {
                    const uint32_t tb = (dy * 3 + dx) * 2048;
                    ldmx4t(Bh[dy][0], wo0 + tb);
                    ldmx4t(Bh[dy][1], wo1 + tb);
                }
                #pragma unroll
                for (int t = 0; t < 6; t++) {
                    uint32_t Ah[4];
                    const int p = (r0 + t) * HALO_W + dx + mbw * 16 + lm;
                    ldmx4(Ah, smb + A_OFF + a_byte(p, kb * 2 + ksel));
                    #pragma unroll
                    for (int dy = 0; dy < 3; dy++) {
                        const int rr = t - dy;
                        if (rr >= 0 && rr < 4) {
                            #pragma unroll
                            for (int np = 0; np < 2; np++) {
                                mma16816h(acc[rr][np * 2],     Ah, &Bh[dy][np][0]);
                                mma16816h(acc[rr][np * 2 + 1], Ah, &Bh[dy][np][2]);
                            }
                        }
                    }
                }
            }
        }
        __syncthreads();   // A free for next tile's fill

        // ---- pipelined fill issue / prefetch for next tile ----
        const int ntile = tile + GRID_P;
        const bool hasn = ntile < NTILES;
        int nb_ = 0, ny0 = 0, nx0 = 0;
        if (hasn) {
            nb_ = ntile >> 7;
            ny0 = ((ntile >> 3) & 15) * TILE_H;
            nx0 = (ntile & 7) * TILE_W;
            if (tid < 16) {
                float g0 = fmaxf(gate[nb_ * 32 + 2 * tid],     0.0f);
                float g1 = fmaxf(gate[nb_ * 32 + 2 * tid + 1], 0.0f);
                ((__half2*)(sm + GATE_OFF))[((it + 1) & 1) * 16 + tid] =
                    __floats2half2_rn(g0, g1);
            }
            if (SECOND) issue_p2(smb, nb_, ny0, nx0, tid);
            else        prefetch_p1(x, nb_, ny0, nx0, tid);
        }

        // ---- epilogue (half2 math) ----
        {
            const __half2* bs2 = (const __half2*)(sm + BIAS_OFF);
            const __half2* gs2 = (const __half2*)(sm + GATE_OFF) + sl * 16;
            __half2 b2[4], g2[4];
            #pragma unroll
            for (int nb = 0; nb < 4; nb++) {
                b2[nb] = bs2[nb * 4 + tig];
                g2[nb] = gs2[nb * 4 + tig];
            }

            #pragma unroll
            for (int rr = 0; rr < 4; rr++) {
                const int y = y0 + r0 + rr;
                #pragma unroll
                for (int half = 0; half < 2; half++) {
                    const int xg = x0 + mbw * 16 + grp + half * 8;
                    const uint32_t obase = ((uint32_t)b << 21) + ((uint32_t)y << 8) + xg;
                    const uint32_t hbase = ((((uint32_t)b << 16) + ((uint32_t)y << 8) + xg) << 4);
                    #pragma unroll
                    for (int nb = 0; nb < 4; nb++) {
                        __half2 a2 = *reinterpret_cast<__half2*>(&acc[rr][nb][half]);
                        __half2 t2 = __hmul2(g2[nb], __hmax2(__hadd2(a2, b2[nb]), hz));
                        if (SECOND) {
                            const int co = nb * 8 + tig * 2;
                            float2 f = __half22float2(t2);
                            uint32_t i0 = obase + (uint32_t)co * 65536u;
                            out[i0]          = f.x + x[i0];
                            out[i0 + 65536u] = f.y + x[i0 + 65536u];
                        } else {
                            const int co = nb * 8 + tig * 2;
                            g_h[hbase + (co >> 1)] = *reinterpret_cast<uint32_t*>(&t2);
                        }
                    }
                }
            }
        }

        // ---- complete next tile's fill ----
        if (hasn) {
            if (SECOND) cpa_waitall();
            else        fill_p1(sm, x, nb_, ny0, nx0, tid);
        }
        __syncthreads();

        tile = ntile;
        it++;
    }
}

extern "C" void kernel_launch(void* const* d_in, const int* in_sizes, int n_in,
                              void* d_out, int out_size)
{
    const float* x    = (const float*)d_in[0];
    const float* gate = (const float*)d_in[1];
    const float* w1   = (const float*)d_in[2];
    const float* b1   = (const float*)d_in[3];
    const float* w2   = (const float*)d_in[4];
    const float* b2   = (const float*)d_in[5];
    float*       out  = (float*)d_out;
    (void)in_sizes; (void)n_in; (void)out_size;

    cudaFuncSetAttribute(conv_hmma<false>,
                         cudaFuncAttributeMaxDynamicSharedMemorySize, SMEM_BYTES);
    cudaFuncSetAttribute(conv_hmma<true>,
                         cudaFuncAttributeMaxDynamicSharedMemorySize, SMEM_BYTES);

    prep_weights<<<72, 256>>>(w1, w2);
    conv_hmma<false><<<GRID_P, THREADS, SMEM_BYTES>>>(x, b1, gate, nullptr);
    conv_hmma<true ><<<GRID_P, THREADS, SMEM_BYTES>>>(x, b2, gate, out);
}